// round 4
// baseline (speedup 1.0000x reference)
#include <cuda_runtime.h>
#include <cstdint>

// ---------------------------------------------------------------------------
// RSSM step, B=32768, STATE=100, BELIEF=200, HID=200, EMB=1024, ACT=32
// Outputs (concatenated): new_belief[B,200], prior_state[B,100],
// prior_mean[B,100], prior_std[B,100], post_state[B,100], post_mean[B,100],
// post_std[B,100]  => out_size = B*800 floats
// ---------------------------------------------------------------------------

#define BROWS   32768
#define NBELIEF 200
#define NSTATE  100

#define BM 128
#define BN 200
#define KC 16
#define GTHREADS 320   // 16 (M groups) x 20 (N groups), microtile 8x10

// ---------------- scratch (static device globals; no allocation) -----------
__device__ float g_h  [(size_t)BROWS * 200];  // relu embed / reused as hq
__device__ float g_g  [(size_t)BROWS * 800];  // GRU pre-activations
__device__ float g_hp [(size_t)BROWS * 200];  // hidden of heads
__device__ float g_p  [(size_t)BROWS * 200];  // head output (mean|std_raw)
__device__ float g_eps[(size_t)BROWS * 100];  // jax.random.normal(key(42))
__device__ float g_wgru[400 * 800];           // packed GRU weights

// ---------------------------------------------------------------------------
// Threefry-2x32 (JAX default PRNG), key = (0, 42).
// PARTITIONABLE path (jax_threefry_partitionable=True, the modern default):
// for element with linear index i: block = (hi32(i), lo32(i)) = (0, i),
// output bits = out0 ^ out1 of that single block.
// ---------------------------------------------------------------------------
#define TFR(r) do { x0 += x1; x1 = (x1 << (r)) | (x1 >> (32 - (r))); x1 ^= x0; } while (0)

__device__ __forceinline__ void threefry2x32_0_42(uint32_t& x0, uint32_t& x1) {
    const uint32_t k0 = 0u;
    const uint32_t k1 = 42u;
    const uint32_t k2 = 0x1BD11BDAu ^ 0u ^ 42u;
    x0 += k0; x1 += k1;
    TFR(13); TFR(15); TFR(26); TFR(6);   x0 += k1; x1 += k2 + 1u;
    TFR(17); TFR(29); TFR(16); TFR(24);  x0 += k2; x1 += k0 + 2u;
    TFR(13); TFR(15); TFR(26); TFR(6);   x0 += k0; x1 += k1 + 3u;
    TFR(17); TFR(29); TFR(16); TFR(24);  x0 += k1; x1 += k2 + 4u;
    TFR(13); TFR(15); TFR(26); TFR(6);   x0 += k2; x1 += k0 + 5u;
}

__device__ __forceinline__ float bits_to_normal(uint32_t bits) {
    // jax _uniform: f = bitcast(bits>>9 | 0x3f800000) - 1  in [0,1)
    float f = __uint_as_float((bits >> 9) | 0x3f800000u) - 1.0f;
    const float lo = -0.99999994f;           // nextafter(-1, 0) in f32
    const float range = 2.0f;                // f32(1.0 - lo) rounds to 2.0
    float u = __fadd_rn(__fmul_rn(f, range), lo);
    u = fmaxf(lo, u);
    return __fmul_rn(1.41421356f, erfinvf(u));   // sqrt(2) as f32
}

__global__ void eps_kernel(float* __restrict__ eps, int n) {
    int i = blockIdx.x * blockDim.x + threadIdx.x;
    if (i >= n) return;
    uint32_t x0 = 0u;              // hi32 of 64-bit linear index
    uint32_t x1 = (uint32_t)i;     // lo32
    threefry2x32_0_42(x0, x1);
    eps[i] = bits_to_normal(x0 ^ x1);
}

// ---------------------------------------------------------------------------
// Pack GRU weights: Wbig[400x800]; A = [x(200) | h(200)]
// cols [0:200)=r  : [W_ir ; W_hr]
// cols [200:400)=z: [W_iz ; W_hz]
// cols [400:600)  : [W_in ; 0   ]   (x-only part of n)
// cols [600:800)  : [0    ; W_hn]   (h-only part of n)
// ---------------------------------------------------------------------------
__global__ void build_wgru_kernel(const float* __restrict__ W_ir, const float* __restrict__ W_iz,
                                  const float* __restrict__ W_in, const float* __restrict__ W_hr,
                                  const float* __restrict__ W_hz, const float* __restrict__ W_hn,
                                  float* __restrict__ wg) {
    int idx = blockIdx.x * blockDim.x + threadIdx.x;
    if (idx >= 400 * 800) return;
    int k = idx / 800, c = idx - k * 800;
    int blk = c / 200, j = c - blk * 200;
    float v = 0.0f;
    if (k < 200) {
        int o = k * 200 + j;
        if (blk == 0) v = W_ir[o];
        else if (blk == 1) v = W_iz[o];
        else if (blk == 2) v = W_in[o];
    } else {
        int o = (k - 200) * 200 + j;
        if (blk == 0) v = W_hr[o];
        else if (blk == 1) v = W_hz[o];
        else if (blk == 3) v = W_hn[o];
    }
    wg[idx] = v;
}

// ---------------------------------------------------------------------------
// Generic fused SGEMM: C[M x N] = act(A_virtual[M x K] @ W[K x N] + bias)
// A_virtual built on the fly (concat / masked inputs).
// Tile BM=128 x BN=200, KC=16, 320 threads, 8x10 microtile.
// ---------------------------------------------------------------------------
enum { AK_PLAIN = 0, AK_SA = 1, AK_GRU = 2, AK_POST = 3 };

template<int AK>
__device__ __forceinline__ float loadA(const float* __restrict__ A0,
                                       const float* __restrict__ A1,
                                       const float* __restrict__ A2,
                                       int row, int k, int lda) {
    if (AK == AK_PLAIN) {
        return A0[(size_t)row * lda + k];
    } else if (AK == AK_SA) {   // [prev_state * nonterm (100) | prev_action (32)]
        return (k < 100) ? A0[(size_t)row * 100 + k] * A2[row]
                         : A1[(size_t)row * 32 + (k - 100)];
    } else if (AK == AK_GRU) {  // [prev_belief (200) | h (200)]
        return (k < 200) ? A0[(size_t)row * 200 + k]
                         : A1[(size_t)row * 200 + (k - 200)];
    } else {                    // AK_POST: [belief (200) | observation (1024)]
        return (k < 200) ? A0[(size_t)row * 200 + k]
                         : A1[(size_t)row * 1024 + (k - 200)];
    }
}

template<int AK, bool RELU, bool HASBIAS>
__global__ void __launch_bounds__(GTHREADS)
gemm_kernel(const float* __restrict__ A0, const float* __restrict__ A1,
            const float* __restrict__ A2,
            const float* __restrict__ W, const float* __restrict__ bias,
            float* __restrict__ C, int K, int lda, int ldw, int ldc) {
    __shared__ float As[KC][BM + 1];   // [k][m], padded vs bank conflicts
    __shared__ float Ws[KC][BN];       // [k][n]

    const int tid  = threadIdx.x;
    const int tm   = tid / 20;         // 0..15 -> rows tm*8 .. tm*8+7
    const int tn   = tid - tm * 20;    // 0..19 -> cols tn*10 .. tn*10+9
    const int row0 = blockIdx.x * BM;
    const int col0 = blockIdx.y * BN;

    float acc[8][10];
    #pragma unroll
    for (int i = 0; i < 8; i++)
        #pragma unroll
        for (int j = 0; j < 10; j++) acc[i][j] = 0.0f;

    for (int k0 = 0; k0 < K; k0 += KC) {
        // stage A tile (BM x KC = 2048 elems)
        for (int e = tid; e < BM * KC; e += GTHREADS) {
            int m = e >> 4, kk = e & 15;
            int k = k0 + kk;
            As[kk][m] = (k < K) ? loadA<AK>(A0, A1, A2, row0 + m, k, lda) : 0.0f;
        }
        // stage W tile (KC x BN = 3200 elems)
        for (int e = tid; e < KC * BN; e += GTHREADS) {
            int kk = e / BN, n = e - kk * BN;
            int k = k0 + kk;
            Ws[kk][n] = (k < K) ? W[(size_t)k * ldw + col0 + n] : 0.0f;
        }
        __syncthreads();

        #pragma unroll
        for (int kk = 0; kk < KC; kk++) {
            float a[8], w[10];
            #pragma unroll
            for (int i = 0; i < 8; i++) a[i] = As[kk][tm * 8 + i];
            #pragma unroll
            for (int j = 0; j < 10; j++) w[j] = Ws[kk][tn * 10 + j];
            #pragma unroll
            for (int i = 0; i < 8; i++)
                #pragma unroll
                for (int j = 0; j < 10; j++)
                    acc[i][j] = fmaf(a[i], w[j], acc[i][j]);
        }
        __syncthreads();
    }

    #pragma unroll
    for (int i = 0; i < 8; i++) {
        int row = row0 + tm * 8 + i;
        #pragma unroll
        for (int j = 0; j < 10; j++) {
            int n = tn * 10 + j;
            float v = acc[i][j];
            if (HASBIAS) v += bias[col0 + n];
            if (RELU)    v = fmaxf(v, 0.0f);
            C[(size_t)row * ldc + col0 + n] = v;
        }
    }
}

// ---------------------------------------------------------------------------
// GRU combine: belief = (1-z)*n + z*h
// ---------------------------------------------------------------------------
__global__ void gru_combine_kernel(const float* __restrict__ g, const float* __restrict__ h,
                                   const float* __restrict__ b_ir, const float* __restrict__ b_iz,
                                   const float* __restrict__ b_in, const float* __restrict__ b_hn,
                                   float* __restrict__ belief) {
    int i = blockIdx.x * blockDim.x + threadIdx.x;
    if (i >= BROWS * 200) return;
    int b = i / 200, j = i - b * 200;
    const float* gr = g + (size_t)b * 800;
    float r  = 1.0f / (1.0f + expf(-(gr[j]       + b_ir[j])));
    float z  = 1.0f / (1.0f + expf(-(gr[200 + j] + b_iz[j])));
    float nn = tanhf(gr[400 + j] + b_in[j] + r * (gr[600 + j] + b_hn[j]));
    float hv = h[i];
    belief[i] = (1.0f - z) * nn + z * hv;
}

// ---------------------------------------------------------------------------
// Distribution epilogue: split mean|std_raw, std = softplus(raw)+0.1,
// state = mean + std * eps
// ---------------------------------------------------------------------------
__global__ void dist_kernel(const float* __restrict__ p, const float* __restrict__ eps,
                            float* __restrict__ st, float* __restrict__ mean,
                            float* __restrict__ stddev) {
    int i = blockIdx.x * blockDim.x + threadIdx.x;
    if (i >= BROWS * 100) return;
    int b = i / 100, d = i - b * 100;
    float m   = p[(size_t)b * 200 + d];
    float raw = p[(size_t)b * 200 + 100 + d];
    float sp  = (raw > 0.0f) ? (raw + log1pf(expf(-raw))) : log1pf(expf(raw));
    float s   = sp + 0.1f;
    mean[i]   = m;
    stddev[i] = s;
    st[i]     = m + s * eps[i];
}

// ---------------------------------------------------------------------------
extern "C" void kernel_launch(void* const* d_in, const int* in_sizes, int n_in,
                              void* d_out, int out_size) {
    const float* prev_state   = (const float*)d_in[0];
    const float* prev_action  = (const float*)d_in[1];
    const float* prev_belief  = (const float*)d_in[2];
    const float* observation  = (const float*)d_in[3];
    const float* nonterminals = (const float*)d_in[4];
    const float* W_sa = (const float*)d_in[5];  const float* b_sa = (const float*)d_in[6];
    const float* W_ir = (const float*)d_in[7];  const float* b_ir = (const float*)d_in[8];
    const float* W_iz = (const float*)d_in[9];  const float* b_iz = (const float*)d_in[10];
    const float* W_in = (const float*)d_in[11]; const float* b_in = (const float*)d_in[12];
    const float* W_hr = (const float*)d_in[13];
    const float* W_hz = (const float*)d_in[14];
    const float* W_hn = (const float*)d_in[15]; const float* b_hn = (const float*)d_in[16];
    const float* W_bp = (const float*)d_in[17]; const float* b_bp = (const float*)d_in[18];
    const float* W_sp = (const float*)d_in[19]; const float* b_sp = (const float*)d_in[20];
    const float* W_bq = (const float*)d_in[21]; const float* b_bq = (const float*)d_in[22];
    const float* W_sq = (const float*)d_in[23]; const float* b_sq = (const float*)d_in[24];

    float* out = (float*)d_out;

    float *h, *g, *hp, *p, *eps, *wgru;
    cudaGetSymbolAddress((void**)&h,    g_h);
    cudaGetSymbolAddress((void**)&g,    g_g);
    cudaGetSymbolAddress((void**)&hp,   g_hp);
    cudaGetSymbolAddress((void**)&p,    g_p);
    cudaGetSymbolAddress((void**)&eps,  g_eps);
    cudaGetSymbolAddress((void**)&wgru, g_wgru);

    const size_t oBelief    = 0;
    const size_t oPriorSt   = (size_t)BROWS * 200;
    const size_t oPriorMean = (size_t)BROWS * 300;
    const size_t oPriorStd  = (size_t)BROWS * 400;
    const size_t oPostSt    = (size_t)BROWS * 500;
    const size_t oPostMean  = (size_t)BROWS * 600;
    const size_t oPostStd   = (size_t)BROWS * 700;

    const int MB = BROWS / BM;   // 256 row blocks

    // 1) eps = jax.random.normal(key(42), (B,100))  — partitionable threefry
    {
        int n = BROWS * 100;
        eps_kernel<<<(n + 255) / 256, 256>>>(eps, n);
    }
    // 2) pack GRU weights
    build_wgru_kernel<<<(400 * 800 + 255) / 256, 256>>>(W_ir, W_iz, W_in, W_hr, W_hz, W_hn, wgru);

    // 3) h = relu([state*nonterm, action] @ W_sa + b_sa)    (K=132)
    gemm_kernel<AK_SA, true, true><<<dim3(MB, 1), GTHREADS>>>(
        prev_state, prev_action, nonterminals, W_sa, b_sa, h, 132, 0, 200, 200);

    // 4) g = [prev_belief, h] @ Wgru                        (K=400, N=800)
    gemm_kernel<AK_GRU, false, false><<<dim3(MB, 4), GTHREADS>>>(
        prev_belief, h, nullptr, wgru, nullptr, g, 400, 0, 800, 800);

    // 5) new_belief (written straight into d_out)
    gru_combine_kernel<<<(BROWS * 200 + 255) / 256, 256>>>(
        g, h, b_ir, b_iz, b_in, b_hn, out + oBelief);

    // 6) hp = relu(belief @ W_bp + b_bp)                    (K=200)
    gemm_kernel<AK_PLAIN, true, true><<<dim3(MB, 1), GTHREADS>>>(
        out + oBelief, nullptr, nullptr, W_bp, b_bp, hp, 200, 200, 200, 200);

    // 7) p = relu(hp @ W_sp + b_sp)                         (K=200)
    gemm_kernel<AK_PLAIN, true, true><<<dim3(MB, 1), GTHREADS>>>(
        hp, nullptr, nullptr, W_sp, b_sp, p, 200, 200, 200, 200);

    // 8) prior distribution outputs
    dist_kernel<<<(BROWS * 100 + 255) / 256, 256>>>(
        p, eps, out + oPriorSt, out + oPriorMean, out + oPriorStd);

    // 9) hq = relu([belief, obs] @ W_bq + b_bq)             (K=1224) -> reuse hp
    gemm_kernel<AK_POST, true, true><<<dim3(MB, 1), GTHREADS>>>(
        out + oBelief, observation, nullptr, W_bq, b_bq, hp, 1224, 0, 200, 200);

    // 10) p = relu(hq @ W_sq + b_sq)                        (K=200)
    gemm_kernel<AK_PLAIN, true, true><<<dim3(MB, 1), GTHREADS>>>(
        hp, nullptr, nullptr, W_sq, b_sq, p, 200, 200, 200, 200);

    // 11) posterior distribution outputs (same eps, as in reference)
    dist_kernel<<<(BROWS * 100 + 255) / 256, 256>>>(
        p, eps, out + oPostSt, out + oPostMean, out + oPostStd);

    (void)in_sizes; (void)n_in; (void)out_size;
}

// round 5
// speedup vs baseline: 1.3124x; 1.3124x over previous
#include <cuda_runtime.h>
#include <cstdint>

// ---------------------------------------------------------------------------
// RSSM step, B=32768. GEMMs run on tensor cores via mma.sync tf32 with the
// 3xTF32 (Dekker split) scheme for fp32-faithful accuracy.
// ---------------------------------------------------------------------------

#define BROWS   32768

#define BM 128
#define BN 200
#define KC 32
#define GTHREADS 256      // 8 warps; warp w owns rows [w*16, w*16+16)

// ---------------- scratch (static device globals; no allocation) -----------
__device__ float g_h  [(size_t)BROWS * 200];
__device__ float g_g  [(size_t)BROWS * 800];
__device__ float g_hp [(size_t)BROWS * 200];
__device__ float g_p  [(size_t)BROWS * 200];
__device__ float g_eps[(size_t)BROWS * 100];
__device__ float g_wgru[400 * 800];

// ---------------------------------------------------------------------------
// Threefry-2x32 (partitionable), key = (0, 42)
// ---------------------------------------------------------------------------
#define TFR(r) do { x0 += x1; x1 = (x1 << (r)) | (x1 >> (32 - (r))); x1 ^= x0; } while (0)

__device__ __forceinline__ void threefry2x32_0_42(uint32_t& x0, uint32_t& x1) {
    const uint32_t k0 = 0u;
    const uint32_t k1 = 42u;
    const uint32_t k2 = 0x1BD11BDAu ^ 0u ^ 42u;
    x0 += k0; x1 += k1;
    TFR(13); TFR(15); TFR(26); TFR(6);   x0 += k1; x1 += k2 + 1u;
    TFR(17); TFR(29); TFR(16); TFR(24);  x0 += k2; x1 += k0 + 2u;
    TFR(13); TFR(15); TFR(26); TFR(6);   x0 += k0; x1 += k1 + 3u;
    TFR(17); TFR(29); TFR(16); TFR(24);  x0 += k1; x1 += k2 + 4u;
    TFR(13); TFR(15); TFR(26); TFR(6);   x0 += k2; x1 += k0 + 5u;
}

__device__ __forceinline__ float bits_to_normal(uint32_t bits) {
    float f = __uint_as_float((bits >> 9) | 0x3f800000u) - 1.0f;
    const float lo = -0.99999994f;
    const float range = 2.0f;
    float u = __fadd_rn(__fmul_rn(f, range), lo);
    u = fmaxf(lo, u);
    return __fmul_rn(1.41421356f, erfinvf(u));
}

__global__ void eps_kernel(float* __restrict__ eps, int n) {
    int i = blockIdx.x * blockDim.x + threadIdx.x;
    if (i >= n) return;
    uint32_t x0 = 0u;
    uint32_t x1 = (uint32_t)i;
    threefry2x32_0_42(x0, x1);
    eps[i] = bits_to_normal(x0 ^ x1);
}

// ---------------------------------------------------------------------------
// Pack GRU weights (see R3)
// ---------------------------------------------------------------------------
__global__ void build_wgru_kernel(const float* __restrict__ W_ir, const float* __restrict__ W_iz,
                                  const float* __restrict__ W_in, const float* __restrict__ W_hr,
                                  const float* __restrict__ W_hz, const float* __restrict__ W_hn,
                                  float* __restrict__ wg) {
    int idx = blockIdx.x * blockDim.x + threadIdx.x;
    if (idx >= 400 * 800) return;
    int k = idx / 800, c = idx - k * 800;
    int blk = c / 200, j = c - blk * 200;
    float v = 0.0f;
    if (k < 200) {
        int o = k * 200 + j;
        if (blk == 0) v = W_ir[o];
        else if (blk == 1) v = W_iz[o];
        else if (blk == 2) v = W_in[o];
    } else {
        int o = (k - 200) * 200 + j;
        if (blk == 0) v = W_hr[o];
        else if (blk == 1) v = W_hz[o];
        else if (blk == 3) v = W_hn[o];
    }
    wg[idx] = v;
}

// ---------------------------------------------------------------------------
// tf32 helpers
// ---------------------------------------------------------------------------
__device__ __forceinline__ uint32_t f32_to_tf32(float x) {
    uint32_t r;
    asm("cvt.rna.tf32.f32 %0, %1;" : "=r"(r) : "f"(x));
    return r;
}

#define MMA_TF32(d, a0, a1, a2, a3, b0, b1)                                   \
    asm volatile(                                                             \
        "mma.sync.aligned.m16n8k8.row.col.f32.tf32.tf32.f32 "                 \
        "{%0,%1,%2,%3}, {%4,%5,%6,%7}, {%8,%9}, {%0,%1,%2,%3};"               \
        : "+f"(d[0]), "+f"(d[1]), "+f"(d[2]), "+f"(d[3])                      \
        : "r"(a0), "r"(a1), "r"(a2), "r"(a3), "r"(b0), "r"(b1))

// ---------------------------------------------------------------------------
// Fused tensor-core SGEMM (3xTF32): C[M x 200/block] = act(A_virt @ W + bias)
// A_virt built on the fly (concat / masked inputs), exactly as the R3 kernel.
// ---------------------------------------------------------------------------
enum { AK_PLAIN = 0, AK_SA = 1, AK_GRU = 2, AK_POST = 3 };

template<int AK>
__device__ __forceinline__ float loadA(const float* __restrict__ A0,
                                       const float* __restrict__ A1,
                                       const float* __restrict__ A2,
                                       int row, int k, int lda) {
    if (AK == AK_PLAIN) {
        return A0[(size_t)row * lda + k];
    } else if (AK == AK_SA) {   // [prev_state * nonterm (100) | prev_action (32)]
        return (k < 100) ? A0[(size_t)row * 100 + k] * A2[row]
                         : A1[(size_t)row * 32 + (k - 100)];
    } else if (AK == AK_GRU) {  // [prev_belief (200) | h (200)]
        return (k < 200) ? A0[(size_t)row * 200 + k]
                         : A1[(size_t)row * 200 + (k - 200)];
    } else {                    // AK_POST: [belief (200) | observation (1024)]
        return (k < 200) ? A0[(size_t)row * 200 + k]
                         : A1[(size_t)row * 1024 + (k - 200)];
    }
}

#define AS_LD 36   // A smem row pitch: 36 mod 32 = 4 -> frag LDS banks 4m+q all distinct

template<int AK, bool RELU, bool HASBIAS>
__global__ void __launch_bounds__(GTHREADS)
gemm_kernel(const float* __restrict__ A0, const float* __restrict__ A1,
            const float* __restrict__ A2,
            const float* __restrict__ W, const float* __restrict__ bias,
            float* __restrict__ C, int K, int lda, int ldw, int ldc) {
    __shared__ float As[BM * AS_LD];   // [m][kk], pitch 36
    __shared__ float Ws[KC * BN];      // [kk][n]

    const int tid  = threadIdx.x;
    const int lane = tid & 31;
    const int wq   = tid >> 5;         // warp id: rows wq*16 .. wq*16+15
    const int g    = lane >> 2;        // 0..7
    const int q    = lane & 3;         // 0..3
    const int row0 = blockIdx.x * BM;
    const int col0 = blockIdx.y * BN;

    float acc[25][4];
    #pragma unroll
    for (int j = 0; j < 25; j++)
        #pragma unroll
        for (int t = 0; t < 4; t++) acc[j][t] = 0.0f;

    const int mrow = wq * 16 + g;

    for (int k0 = 0; k0 < K; k0 += KC) {
        // stage A tile: 128x32, coalesced gmem (lane -> consecutive k)
        #pragma unroll
        for (int e = tid; e < BM * KC; e += GTHREADS) {
            int m  = e >> 5;           // e / 32
            int kk = e & 31;
            int k  = k0 + kk;
            As[m * AS_LD + kk] = (k < K) ? loadA<AK>(A0, A1, A2, row0 + m, k, lda) : 0.0f;
        }
        // stage W tile: 32x200, coalesced gmem (lane -> consecutive n)
        #pragma unroll
        for (int e = tid; e < KC * BN; e += GTHREADS) {
            int kk = e / BN, n = e - kk * BN;
            int k  = k0 + kk;
            Ws[kk * BN + n] = (k < K) ? W[(size_t)k * ldw + col0 + n] : 0.0f;
        }
        __syncthreads();

        #pragma unroll
        for (int kk = 0; kk < KC; kk += 8) {
            // A fragment (m16k8): rows mrow/mrow+8, cols kk+q / kk+q+4
            float af[4];
            af[0] = As[mrow * AS_LD + kk + q];
            af[1] = As[(mrow + 8) * AS_LD + kk + q];
            af[2] = As[mrow * AS_LD + kk + q + 4];
            af[3] = As[(mrow + 8) * AS_LD + kk + q + 4];
            uint32_t ah[4], al[4];
            #pragma unroll
            for (int t = 0; t < 4; t++) {
                ah[t] = f32_to_tf32(af[t]);
                al[t] = f32_to_tf32(af[t] - __uint_as_float(ah[t]));
            }
            #pragma unroll
            for (int j = 0; j < 25; j++) {
                // B fragment (k8n8): rows kk+q / kk+q+4, col j*8+g
                float b0f = Ws[(kk + q) * BN + j * 8 + g];
                float b1f = Ws[(kk + q + 4) * BN + j * 8 + g];
                uint32_t bh0 = f32_to_tf32(b0f);
                uint32_t bh1 = f32_to_tf32(b1f);
                uint32_t bl0 = f32_to_tf32(b0f - __uint_as_float(bh0));
                uint32_t bl1 = f32_to_tf32(b1f - __uint_as_float(bh1));
                MMA_TF32(acc[j], ah[0], ah[1], ah[2], ah[3], bh0, bh1);
                MMA_TF32(acc[j], al[0], al[1], al[2], al[3], bh0, bh1);
                MMA_TF32(acc[j], ah[0], ah[1], ah[2], ah[3], bl0, bl1);
            }
        }
        __syncthreads();
    }

    // epilogue: c0/c1 -> (row=mrow, cols 2q,2q+1), c2/c3 -> row=mrow+8
    const int r0 = row0 + mrow;
    #pragma unroll
    for (int j = 0; j < 25; j++) {
        int col = col0 + j * 8 + 2 * q;
        float v0 = acc[j][0], v1 = acc[j][1], v2 = acc[j][2], v3 = acc[j][3];
        if (HASBIAS) {
            float bb0 = bias[col], bb1 = bias[col + 1];
            v0 += bb0; v1 += bb1; v2 += bb0; v3 += bb1;
        }
        if (RELU) {
            v0 = fmaxf(v0, 0.0f); v1 = fmaxf(v1, 0.0f);
            v2 = fmaxf(v2, 0.0f); v3 = fmaxf(v3, 0.0f);
        }
        *(float2*)&C[(size_t)r0 * ldc + col]       = make_float2(v0, v1);
        *(float2*)&C[(size_t)(r0 + 8) * ldc + col] = make_float2(v2, v3);
    }
}

// ---------------------------------------------------------------------------
// GRU combine: belief = (1-z)*n + z*h
// ---------------------------------------------------------------------------
__global__ void gru_combine_kernel(const float* __restrict__ g, const float* __restrict__ h,
                                   const float* __restrict__ b_ir, const float* __restrict__ b_iz,
                                   const float* __restrict__ b_in, const float* __restrict__ b_hn,
                                   float* __restrict__ belief) {
    int i = blockIdx.x * blockDim.x + threadIdx.x;
    if (i >= BROWS * 200) return;
    int b = i / 200, j = i - b * 200;
    const float* gr = g + (size_t)b * 800;
    float r  = 1.0f / (1.0f + expf(-(gr[j]       + b_ir[j])));
    float z  = 1.0f / (1.0f + expf(-(gr[200 + j] + b_iz[j])));
    float nn = tanhf(gr[400 + j] + b_in[j] + r * (gr[600 + j] + b_hn[j]));
    float hv = h[i];
    belief[i] = (1.0f - z) * nn + z * hv;
}

// ---------------------------------------------------------------------------
// Distribution epilogue
// ---------------------------------------------------------------------------
__global__ void dist_kernel(const float* __restrict__ p, const float* __restrict__ eps,
                            float* __restrict__ st, float* __restrict__ mean,
                            float* __restrict__ stddev) {
    int i = blockIdx.x * blockDim.x + threadIdx.x;
    if (i >= BROWS * 100) return;
    int b = i / 100, d = i - b * 100;
    float m   = p[(size_t)b * 200 + d];
    float raw = p[(size_t)b * 200 + 100 + d];
    float sp  = (raw > 0.0f) ? (raw + log1pf(expf(-raw))) : log1pf(expf(raw));
    float s   = sp + 0.1f;
    mean[i]   = m;
    stddev[i] = s;
    st[i]     = m + s * eps[i];
}

// ---------------------------------------------------------------------------
extern "C" void kernel_launch(void* const* d_in, const int* in_sizes, int n_in,
                              void* d_out, int out_size) {
    const float* prev_state   = (const float*)d_in[0];
    const float* prev_action  = (const float*)d_in[1];
    const float* prev_belief  = (const float*)d_in[2];
    const float* observation  = (const float*)d_in[3];
    const float* nonterminals = (const float*)d_in[4];
    const float* W_sa = (const float*)d_in[5];  const float* b_sa = (const float*)d_in[6];
    const float* W_ir = (const float*)d_in[7];  const float* b_ir = (const float*)d_in[8];
    const float* W_iz = (const float*)d_in[9];  const float* b_iz = (const float*)d_in[10];
    const float* W_in = (const float*)d_in[11]; const float* b_in = (const float*)d_in[12];
    const float* W_hr = (const float*)d_in[13];
    const float* W_hz = (const float*)d_in[14];
    const float* W_hn = (const float*)d_in[15]; const float* b_hn = (const float*)d_in[16];
    const float* W_bp = (const float*)d_in[17]; const float* b_bp = (const float*)d_in[18];
    const float* W_sp = (const float*)d_in[19]; const float* b_sp = (const float*)d_in[20];
    const float* W_bq = (const float*)d_in[21]; const float* b_bq = (const float*)d_in[22];
    const float* W_sq = (const float*)d_in[23]; const float* b_sq = (const float*)d_in[24];

    float* out = (float*)d_out;

    float *h, *g, *hp, *p, *eps, *wgru;
    cudaGetSymbolAddress((void**)&h,    g_h);
    cudaGetSymbolAddress((void**)&g,    g_g);
    cudaGetSymbolAddress((void**)&hp,   g_hp);
    cudaGetSymbolAddress((void**)&p,    g_p);
    cudaGetSymbolAddress((void**)&eps,  g_eps);
    cudaGetSymbolAddress((void**)&wgru, g_wgru);

    const size_t oBelief    = 0;
    const size_t oPriorSt   = (size_t)BROWS * 200;
    const size_t oPriorMean = (size_t)BROWS * 300;
    const size_t oPriorStd  = (size_t)BROWS * 400;
    const size_t oPostSt    = (size_t)BROWS * 500;
    const size_t oPostMean  = (size_t)BROWS * 600;
    const size_t oPostStd   = (size_t)BROWS * 700;

    const int MB = BROWS / BM;   // 256 row blocks

    // 1) eps = jax.random.normal(key(42), (B,100))  — partitionable threefry
    {
        int n = BROWS * 100;
        eps_kernel<<<(n + 255) / 256, 256>>>(eps, n);
    }
    // 2) pack GRU weights
    build_wgru_kernel<<<(400 * 800 + 255) / 256, 256>>>(W_ir, W_iz, W_in, W_hr, W_hz, W_hn, wgru);

    // 3) h = relu([state*nonterm, action] @ W_sa + b_sa)    (K=132)
    gemm_kernel<AK_SA, true, true><<<dim3(MB, 1), GTHREADS>>>(
        prev_state, prev_action, nonterminals, W_sa, b_sa, h, 132, 0, 200, 200);

    // 4) g = [prev_belief, h] @ Wgru                        (K=400, N=800)
    gemm_kernel<AK_GRU, false, false><<<dim3(MB, 4), GTHREADS>>>(
        prev_belief, h, nullptr, wgru, nullptr, g, 400, 0, 800, 800);

    // 5) new_belief (written straight into d_out)
    gru_combine_kernel<<<(BROWS * 200 + 255) / 256, 256>>>(
        g, h, b_ir, b_iz, b_in, b_hn, out + oBelief);

    // 6) hp = relu(belief @ W_bp + b_bp)                    (K=200)
    gemm_kernel<AK_PLAIN, true, true><<<dim3(MB, 1), GTHREADS>>>(
        out + oBelief, nullptr, nullptr, W_bp, b_bp, hp, 200, 200, 200, 200);

    // 7) p = relu(hp @ W_sp + b_sp)                         (K=200)
    gemm_kernel<AK_PLAIN, true, true><<<dim3(MB, 1), GTHREADS>>>(
        hp, nullptr, nullptr, W_sp, b_sp, p, 200, 200, 200, 200);

    // 8) prior distribution outputs
    dist_kernel<<<(BROWS * 100 + 255) / 256, 256>>>(
        p, eps, out + oPriorSt, out + oPriorMean, out + oPriorStd);

    // 9) hq = relu([belief, obs] @ W_bq + b_bq)             (K=1224) -> reuse hp
    gemm_kernel<AK_POST, true, true><<<dim3(MB, 1), GTHREADS>>>(
        out + oBelief, observation, nullptr, W_bq, b_bq, hp, 1224, 0, 200, 200);

    // 10) p = relu(hq @ W_sq + b_sq)                        (K=200)
    gemm_kernel<AK_PLAIN, true, true><<<dim3(MB, 1), GTHREADS>>>(
        hp, nullptr, nullptr, W_sq, b_sq, p, 200, 200, 200, 200);

    // 11) posterior distribution outputs (same eps, as in reference)
    dist_kernel<<<(BROWS * 100 + 255) / 256, 256>>>(
        p, eps, out + oPostSt, out + oPostMean, out + oPostStd);

    (void)in_sizes; (void)n_in; (void)out_size;
}

// round 7
// speedup vs baseline: 2.3762x; 1.8107x over previous
#include <cuda_runtime.h>
#include <cstdint>

// ---------------------------------------------------------------------------
// RSSM step, B=32768. Tensor-core 3xTF32 GEMMs with pre-split weights,
// double-buffered smem pipeline, 4x2 warp tiling.
// ---------------------------------------------------------------------------

#define BROWS   32768

#define BM 64
#define BN 200
#define KC 16
#define GTHREADS 256      // 8 warps: 4 in M (16 rows each) x 2 in N (13/12 frags)

#define AS_PITCH 20       // A smem pitch: 20g+q covers all 32 banks
#define AS_BUF   (BM * AS_PITCH)        // 1280 floats per buffer
#define WS_BUF   (KC * BN)              // 3200 floats per buffer
#define SMEM_FLOATS (2*AS_BUF + 4*WS_BUF)   // As x2, Wh x2, Wl x2
#define SMEM_BYTES (SMEM_FLOATS * 4)        // 61440

// ---------------- scratch (static device globals; no allocation) -----------
__device__ float g_h   [(size_t)BROWS * 200];
__device__ float g_g   [(size_t)BROWS * 800];
__device__ float g_hp  [(size_t)BROWS * 200];
__device__ float g_p   [(size_t)BROWS * 200];
__device__ float g_eps [(size_t)BROWS * 100];
__device__ float g_sm  [(size_t)BROWS * 100];   // prev_state * nonterminals
__device__ float g_wgru[400 * 800];
// pre-split weights (tf32 hi/lo), segment offsets below
#define OFF_SA  0
#define LEN_SA  (132*200)
#define OFF_GRU (OFF_SA + LEN_SA)
#define LEN_GRU (400*800)
#define OFF_BP  (OFF_GRU + LEN_GRU)
#define LEN_BP  (200*200)
#define OFF_SP  (OFF_BP + LEN_BP)
#define LEN_SP  (200*200)
#define OFF_BQ  (OFF_SP + LEN_SP)
#define LEN_BQ  (1224*200)
#define OFF_SQ  (OFF_BQ + LEN_BQ)
#define LEN_SQ  (200*200)
#define WTOTAL  (OFF_SQ + LEN_SQ)
__device__ float g_whi[WTOTAL];
__device__ float g_wlo[WTOTAL];

// ---------------------------------------------------------------------------
// Threefry-2x32 (partitionable), key = (0, 42)
// ---------------------------------------------------------------------------
#define TFR(r) do { x0 += x1; x1 = (x1 << (r)) | (x1 >> (32 - (r))); x1 ^= x0; } while (0)

__device__ __forceinline__ void threefry2x32_0_42(uint32_t& x0, uint32_t& x1) {
    const uint32_t k0 = 0u;
    const uint32_t k1 = 42u;
    const uint32_t k2 = 0x1BD11BDAu ^ 0u ^ 42u;
    x0 += k0; x1 += k1;
    TFR(13); TFR(15); TFR(26); TFR(6);   x0 += k1; x1 += k2 + 1u;
    TFR(17); TFR(29); TFR(16); TFR(24);  x0 += k2; x1 += k0 + 2u;
    TFR(13); TFR(15); TFR(26); TFR(6);   x0 += k0; x1 += k1 + 3u;
    TFR(17); TFR(29); TFR(16); TFR(24);  x0 += k1; x1 += k2 + 4u;
    TFR(13); TFR(15); TFR(26); TFR(6);   x0 += k2; x1 += k0 + 5u;
}

__device__ __forceinline__ float bits_to_normal(uint32_t bits) {
    float f = __uint_as_float((bits >> 9) | 0x3f800000u) - 1.0f;
    const float lo = -0.99999994f;
    const float range = 2.0f;
    float u = __fadd_rn(__fmul_rn(f, range), lo);
    u = fmaxf(lo, u);
    return __fmul_rn(1.41421356f, erfinvf(u));
}

__global__ void eps_kernel(float* __restrict__ eps, int n) {
    int i = blockIdx.x * blockDim.x + threadIdx.x;
    if (i >= n) return;
    uint32_t x0 = 0u;
    uint32_t x1 = (uint32_t)i;
    threefry2x32_0_42(x0, x1);
    eps[i] = bits_to_normal(x0 ^ x1);
}

// ---------------------------------------------------------------------------
// Weight prep: GRU pack + tf32 hi/lo split
// ---------------------------------------------------------------------------
__global__ void build_wgru_kernel(const float* __restrict__ W_ir, const float* __restrict__ W_iz,
                                  const float* __restrict__ W_in, const float* __restrict__ W_hr,
                                  const float* __restrict__ W_hz, const float* __restrict__ W_hn,
                                  float* __restrict__ wg) {
    int idx = blockIdx.x * blockDim.x + threadIdx.x;
    if (idx >= 400 * 800) return;
    int k = idx / 800, c = idx - k * 800;
    int blk = c / 200, j = c - blk * 200;
    float v = 0.0f;
    if (k < 200) {
        int o = k * 200 + j;
        if (blk == 0) v = W_ir[o];
        else if (blk == 1) v = W_iz[o];
        else if (blk == 2) v = W_in[o];
    } else {
        int o = (k - 200) * 200 + j;
        if (blk == 0) v = W_hr[o];
        else if (blk == 1) v = W_hz[o];
        else if (blk == 3) v = W_hn[o];
    }
    wg[idx] = v;
}

__device__ __forceinline__ uint32_t f32_to_tf32(float x) {
    uint32_t r;
    asm("cvt.rna.tf32.f32 %0, %1;" : "=r"(r) : "f"(x));
    return r;
}

__global__ void split_kernel(const float* __restrict__ src, float* __restrict__ hi,
                             float* __restrict__ lo, int n) {
    int i = blockIdx.x * blockDim.x + threadIdx.x;
    if (i >= n) return;
    float w = src[i];
    uint32_t h = f32_to_tf32(w);
    float hf = __uint_as_float(h);
    uint32_t l = f32_to_tf32(w - hf);
    hi[i] = hf;
    lo[i] = __uint_as_float(l);
}

__global__ void premult_kernel(const float* __restrict__ st, const float* __restrict__ nt,
                               float* __restrict__ out, int n) {
    int i = blockIdx.x * blockDim.x + threadIdx.x;
    if (i >= n) return;
    out[i] = st[i] * nt[i / 100];
}

// ---------------------------------------------------------------------------
// Tensor-core GEMM: C = act(concat(A0[.,c0], A1[.,c1]) @ W + bias)
// W given pre-split as Wh/Wl (tf32 values stored as f32).
// ---------------------------------------------------------------------------
#define MMA_TF32(d, a0, a1, a2, a3, b0, b1)                                   \
    asm volatile(                                                             \
        "mma.sync.aligned.m16n8k8.row.col.f32.tf32.tf32.f32 "                 \
        "{%0,%1,%2,%3}, {%4,%5,%6,%7}, {%8,%9}, {%0,%1,%2,%3};"               \
        : "+f"(d[0]), "+f"(d[1]), "+f"(d[2]), "+f"(d[3])                      \
        : "r"(a0), "r"(a1), "r"(a2), "r"(a3), "r"(b0), "r"(b1))

template<bool RELU, bool HASBIAS>
__global__ void __launch_bounds__(GTHREADS, 2)
gemm_kernel(const float* __restrict__ A0, const float* __restrict__ A1,
            int c0, int c1,
            const float* __restrict__ Wh, const float* __restrict__ Wl,
            const float* __restrict__ bias,
            float* __restrict__ C, int K, int ldw, int ldc) {
    extern __shared__ float smem[];
    float* As = smem;                    // [2][BM][AS_PITCH]
    float* Whs = smem + 2 * AS_BUF;      // [2][KC][BN]
    float* Wls = Whs + 2 * WS_BUF;       // [2][KC][BN]

    const int tid  = threadIdx.x;
    const int lane = tid & 31;
    const int wq   = tid >> 5;
    const int mq   = wq >> 1;            // 0..3
    const int nq   = wq & 1;             // 0..1
    const int g    = lane >> 2;
    const int q    = lane & 3;
    const int row0 = blockIdx.x * BM;
    const int col0 = blockIdx.y * BN;
    const int j0   = nq * 13;            // nq=0: j 0..12 ; nq=1: j 13..24
    const int mrow = mq * 16 + g;

    float acc[13][4];
    #pragma unroll
    for (int j = 0; j < 13; j++)
        #pragma unroll
        for (int t = 0; t < 4; t++) acc[j][t] = 0.0f;

    const int ntiles = (K + KC - 1) / KC;

    // ---- stage tile 0 directly to smem buffer 0 ----
    {
        #pragma unroll
        for (int i = 0; i < 4; i++) {
            int e = tid + i * GTHREADS;          // < 1024
            int m = e >> 4, kk = e & 15;
            int k = kk;                          // k0 = 0
            int row = row0 + m;
            float v = 0.0f;
            if (k < K) v = (k < c0) ? A0[(size_t)row * c0 + k]
                                    : A1[(size_t)row * c1 + (k - c0)];
            As[m * AS_PITCH + kk] = v;
        }
        #pragma unroll
        for (int i = 0; i < 13; i++) {
            int e = tid + i * GTHREADS;
            if (e < KC * BN) {
                int kk = e / BN, n = e - kk * BN;
                float vh = 0.0f, vl = 0.0f;
                if (kk < K) {
                    size_t off = (size_t)kk * ldw + col0 + n;
                    vh = Wh[off]; vl = Wl[off];
                }
                Whs[kk * BN + n] = vh;
                Wls[kk * BN + n] = vl;
            }
        }
    }
    __syncthreads();

    for (int t = 0; t < ntiles; t++) {
        const int buf = t & 1;
        const bool has_next = (t + 1 < ntiles);

        // ---- prefetch next tile gmem -> regs ----
        float a_pf[4];
        float wh_pf[13], wl_pf[13];
        if (has_next) {
            int k0n = (t + 1) * KC;
            #pragma unroll
            for (int i = 0; i < 4; i++) {
                int e = tid + i * GTHREADS;
                int m = e >> 4, kk = e & 15;
                int k = k0n + kk;
                int row = row0 + m;
                float v = 0.0f;
                if (k < K) v = (k < c0) ? A0[(size_t)row * c0 + k]
                                        : A1[(size_t)row * c1 + (k - c0)];
                a_pf[i] = v;
            }
            #pragma unroll
            for (int i = 0; i < 13; i++) {
                int e = tid + i * GTHREADS;
                wh_pf[i] = 0.0f; wl_pf[i] = 0.0f;
                if (e < KC * BN) {
                    int kk = e / BN, n = e - kk * BN;
                    int k = k0n + kk;
                    if (k < K) {
                        size_t off = (size_t)k * ldw + col0 + n;
                        wh_pf[i] = Wh[off];
                        wl_pf[i] = Wl[off];
                    }
                }
            }
        }

        // ---- compute from smem[buf] ----
        const float* Ab = As + buf * AS_BUF;
        const float* Whb = Whs + buf * WS_BUF;
        const float* Wlb = Wls + buf * WS_BUF;
        #pragma unroll
        for (int kk = 0; kk < KC; kk += 8) {
            float af0 = Ab[mrow * AS_PITCH + kk + q];
            float af1 = Ab[(mrow + 8) * AS_PITCH + kk + q];
            float af2 = Ab[mrow * AS_PITCH + kk + q + 4];
            float af3 = Ab[(mrow + 8) * AS_PITCH + kk + q + 4];
            uint32_t ah0 = f32_to_tf32(af0), ah1 = f32_to_tf32(af1);
            uint32_t ah2 = f32_to_tf32(af2), ah3 = f32_to_tf32(af3);
            uint32_t al0 = f32_to_tf32(af0 - __uint_as_float(ah0));
            uint32_t al1 = f32_to_tf32(af1 - __uint_as_float(ah1));
            uint32_t al2 = f32_to_tf32(af2 - __uint_as_float(ah2));
            uint32_t al3 = f32_to_tf32(af3 - __uint_as_float(ah3));
            #pragma unroll
            for (int j = 0; j < 13; j++) {
                if (j0 + j < 25) {
                    int n = (j0 + j) * 8 + g;
                    uint32_t bh0 = __float_as_uint(Whb[(kk + q) * BN + n]);
                    uint32_t bh1 = __float_as_uint(Whb[(kk + q + 4) * BN + n]);
                    uint32_t bl0 = __float_as_uint(Wlb[(kk + q) * BN + n]);
                    uint32_t bl1 = __float_as_uint(Wlb[(kk + q + 4) * BN + n]);
                    MMA_TF32(acc[j], ah0, ah1, ah2, ah3, bh0, bh1);
                    MMA_TF32(acc[j], al0, al1, al2, al3, bh0, bh1);
                    MMA_TF32(acc[j], ah0, ah1, ah2, ah3, bl0, bl1);
                }
            }
        }

        // ---- store prefetched tile into the other buffer ----
        if (has_next) {
            const int nb = buf ^ 1;
            float* An = As + nb * AS_BUF;
            float* Whn = Whs + nb * WS_BUF;
            float* Wln = Wls + nb * WS_BUF;
            #pragma unroll
            for (int i = 0; i < 4; i++) {
                int e = tid + i * GTHREADS;
                int m = e >> 4, kk = e & 15;
                An[m * AS_PITCH + kk] = a_pf[i];
            }
            #pragma unroll
            for (int i = 0; i < 13; i++) {
                int e = tid + i * GTHREADS;
                if (e < KC * BN) {
                    int kk = e / BN, n = e - kk * BN;
                    Whn[kk * BN + n] = wh_pf[i];
                    Wln[kk * BN + n] = wl_pf[i];
                }
            }
        }
        __syncthreads();
    }

    // ---- epilogue ----
    const int r0 = row0 + mrow;
    #pragma unroll
    for (int j = 0; j < 13; j++) {
        if (j0 + j < 25) {
            int col = col0 + (j0 + j) * 8 + 2 * q;
            float v0 = acc[j][0], v1 = acc[j][1], v2 = acc[j][2], v3 = acc[j][3];
            if (HASBIAS) {
                float bb0 = bias[col], bb1 = bias[col + 1];
                v0 += bb0; v1 += bb1; v2 += bb0; v3 += bb1;
            }
            if (RELU) {
                v0 = fmaxf(v0, 0.0f); v1 = fmaxf(v1, 0.0f);
                v2 = fmaxf(v2, 0.0f); v3 = fmaxf(v3, 0.0f);
            }
            *(float2*)&C[(size_t)r0 * ldc + col]       = make_float2(v0, v1);
            *(float2*)&C[(size_t)(r0 + 8) * ldc + col] = make_float2(v2, v3);
        }
    }
}

// ---------------------------------------------------------------------------
// GRU combine: belief = (1-z)*n + z*h
// ---------------------------------------------------------------------------
__global__ void gru_combine_kernel(const float* __restrict__ g, const float* __restrict__ h,
                                   const float* __restrict__ b_ir, const float* __restrict__ b_iz,
                                   const float* __restrict__ b_in, const float* __restrict__ b_hn,
                                   float* __restrict__ belief) {
    int i = blockIdx.x * blockDim.x + threadIdx.x;
    if (i >= BROWS * 200) return;
    int b = i / 200, j = i - b * 200;
    const float* gr = g + (size_t)b * 800;
    float r  = 1.0f / (1.0f + expf(-(gr[j]       + b_ir[j])));
    float z  = 1.0f / (1.0f + expf(-(gr[200 + j] + b_iz[j])));
    float nn = tanhf(gr[400 + j] + b_in[j] + r * (gr[600 + j] + b_hn[j]));
    float hv = h[i];
    belief[i] = (1.0f - z) * nn + z * hv;
}

// ---------------------------------------------------------------------------
// Distribution epilogue
// ---------------------------------------------------------------------------
__global__ void dist_kernel(const float* __restrict__ p, const float* __restrict__ eps,
                            float* __restrict__ st, float* __restrict__ mean,
                            float* __restrict__ stddev) {
    int i = blockIdx.x * blockDim.x + threadIdx.x;
    if (i >= BROWS * 100) return;
    int b = i / 100, d = i - b * 100;
    float m   = p[(size_t)b * 200 + d];
    float raw = p[(size_t)b * 200 + 100 + d];
    float sp  = (raw > 0.0f) ? (raw + log1pf(expf(-raw))) : log1pf(expf(raw));
    float s   = sp + 0.1f;
    mean[i]   = m;
    stddev[i] = s;
    st[i]     = m + s * eps[i];
}

// ---------------------------------------------------------------------------
extern "C" void kernel_launch(void* const* d_in, const int* in_sizes, int n_in,
                              void* d_out, int out_size) {
    const float* prev_state   = (const float*)d_in[0];
    const float* prev_action  = (const float*)d_in[1];
    const float* prev_belief  = (const float*)d_in[2];
    const float* observation  = (const float*)d_in[3];
    const float* nonterminals = (const float*)d_in[4];
    const float* W_sa = (const float*)d_in[5];  const float* b_sa = (const float*)d_in[6];
    const float* W_ir = (const float*)d_in[7];  const float* b_ir = (const float*)d_in[8];
    const float* W_iz = (const float*)d_in[9];  const float* b_iz = (const float*)d_in[10];
    const float* W_in = (const float*)d_in[11]; const float* b_in = (const float*)d_in[12];
    const float* W_hr = (const float*)d_in[13];
    const float* W_hz = (const float*)d_in[14];
    const float* W_hn = (const float*)d_in[15]; const float* b_hn = (const float*)d_in[16];
    const float* W_bp = (const float*)d_in[17]; const float* b_bp = (const float*)d_in[18];
    const float* W_sp = (const float*)d_in[19]; const float* b_sp = (const float*)d_in[20];
    const float* W_bq = (const float*)d_in[21]; const float* b_bq = (const float*)d_in[22];
    const float* W_sq = (const float*)d_in[23]; const float* b_sq = (const float*)d_in[24];

    float* out = (float*)d_out;

    float *h, *g, *hp, *p, *eps, *sm, *wgru, *whi, *wlo;
    cudaGetSymbolAddress((void**)&h,    g_h);
    cudaGetSymbolAddress((void**)&g,    g_g);
    cudaGetSymbolAddress((void**)&hp,   g_hp);
    cudaGetSymbolAddress((void**)&p,    g_p);
    cudaGetSymbolAddress((void**)&eps,  g_eps);
    cudaGetSymbolAddress((void**)&sm,   g_sm);
    cudaGetSymbolAddress((void**)&wgru, g_wgru);
    cudaGetSymbolAddress((void**)&whi,  g_whi);
    cudaGetSymbolAddress((void**)&wlo,  g_wlo);

    cudaFuncSetAttribute(gemm_kernel<true, true>,
                         cudaFuncAttributeMaxDynamicSharedMemorySize, SMEM_BYTES);
    cudaFuncSetAttribute(gemm_kernel<false, false>,
                         cudaFuncAttributeMaxDynamicSharedMemorySize, SMEM_BYTES);

    const size_t oBelief    = 0;
    const size_t oPriorSt   = (size_t)BROWS * 200;
    const size_t oPriorMean = (size_t)BROWS * 300;
    const size_t oPriorStd  = (size_t)BROWS * 400;
    const size_t oPostSt    = (size_t)BROWS * 500;
    const size_t oPostMean  = (size_t)BROWS * 600;
    const size_t oPostStd   = (size_t)BROWS * 700;

    const int MB = BROWS / BM;   // 512 row blocks

    // ---- prep: eps, masked state, packed+split weights ----
    {
        int n = BROWS * 100;
        eps_kernel<<<(n + 255) / 256, 256>>>(eps, n);
        premult_kernel<<<(n + 255) / 256, 256>>>(prev_state, nonterminals, sm, n);
    }
    build_wgru_kernel<<<(400 * 800 + 255) / 256, 256>>>(W_ir, W_iz, W_in, W_hr, W_hz, W_hn, wgru);

    split_kernel<<<(LEN_SA  + 255) / 256, 256>>>(W_sa, whi + OFF_SA,  wlo + OFF_SA,  LEN_SA);
    split_kernel<<<(LEN_GRU + 255) / 256, 256>>>(wgru, whi + OFF_GRU, wlo + OFF_GRU, LEN_GRU);
    split_kernel<<<(LEN_BP  + 255) / 256, 256>>>(W_bp, whi + OFF_BP,  wlo + OFF_BP,  LEN_BP);
    split_kernel<<<(LEN_SP  + 255) / 256, 256>>>(W_sp, whi + OFF_SP,  wlo + OFF_SP,  LEN_SP);
    split_kernel<<<(LEN_BQ  + 255) / 256, 256>>>(W_bq, whi + OFF_BQ,  wlo + OFF_BQ,  LEN_BQ);
    split_kernel<<<(LEN_SQ  + 255) / 256, 256>>>(W_sq, whi + OFF_SQ,  wlo + OFF_SQ,  LEN_SQ);

    // 3) h = relu([sm, action] @ W_sa + b_sa)   (K=132)
    gemm_kernel<true, true><<<dim3(MB, 1), GTHREADS, SMEM_BYTES>>>(
        sm, prev_action, 100, 32, whi + OFF_SA, wlo + OFF_SA, b_sa, h, 132, 200, 200);

    // 4) g = [prev_belief, h] @ Wgru            (K=400, N=800)
    gemm_kernel<false, false><<<dim3(MB, 4), GTHREADS, SMEM_BYTES>>>(
        prev_belief, h, 200, 200, whi + OFF_GRU, wlo + OFF_GRU, nullptr, g, 400, 800, 800);

    // 5) new_belief
    gru_combine_kernel<<<(BROWS * 200 + 255) / 256, 256>>>(
        g, h, b_ir, b_iz, b_in, b_hn, out + oBelief);

    // 6) hp = relu(belief @ W_bp + b_bp)        (K=200)
    gemm_kernel<true, true><<<dim3(MB, 1), GTHREADS, SMEM_BYTES>>>(
        out + oBelief, out + oBelief, 200, 200, whi + OFF_BP, wlo + OFF_BP, b_bp, hp, 200, 200, 200);

    // 7) p = relu(hp @ W_sp + b_sp)             (K=200)
    gemm_kernel<true, true><<<dim3(MB, 1), GTHREADS, SMEM_BYTES>>>(
        hp, hp, 200, 200, whi + OFF_SP, wlo + OFF_SP, b_sp, p, 200, 200, 200);

    // 8) prior outputs
    dist_kernel<<<(BROWS * 100 + 255) / 256, 256>>>(
        p, eps, out + oPriorSt, out + oPriorMean, out + oPriorStd);

    // 9) hq = relu([belief, obs] @ W_bq + b_bq) (K=1224)
    gemm_kernel<true, true><<<dim3(MB, 1), GTHREADS, SMEM_BYTES>>>(
        out + oBelief, observation, 200, 1024, whi + OFF_BQ, wlo + OFF_BQ, b_bq, hp, 1224, 200, 200);

    // 10) p = relu(hq @ W_sq + b_sq)            (K=200)
    gemm_kernel<true, true><<<dim3(MB, 1), GTHREADS, SMEM_BYTES>>>(
        hp, hp, 200, 200, whi + OFF_SQ, wlo + OFF_SQ, b_sq, p, 200, 200, 200);

    // 11) posterior outputs
    dist_kernel<<<(BROWS * 100 + 255) / 256, 256>>>(
        p, eps, out + oPostSt, out + oPostMean, out + oPostStd);

    (void)in_sizes; (void)n_in; (void)out_size;
}

// round 12
// speedup vs baseline: 4.4787x; 1.8848x over previous
#include <cuda_runtime.h>
#include <cuda_bf16.h>
#include <cstdint>

// ---------------------------------------------------------------------------
// RSSM step, B=32768. GEMMs via warp-level mma.sync m16n8k16 bf16, with
// error-free-ish bf16x2 splits (3 terms), cp.async W staging, double buffer.
// ---------------------------------------------------------------------------

#define BROWS 32768
#define BM 64
#define BN 200
#define KC 32
#define GTHREADS 256     // 8 warps: 4(M) x 2(N)

// smem layout in u32 units
#define AS_P   20                      // A pitch (u32) -> conflict-free frags
#define AS_SZ  (BM * AS_P)             // 1280 u32 per split-plane
#define WS_SZ  (16 * BN)               // 3200 u32 per split-plane (16 k2 rows)
#define OFF_A(buf, s) (((buf)*2 + (s)) * AS_SZ)
#define OFF_W(buf, s) (4 * AS_SZ + ((buf)*2 + (s)) * WS_SZ)
#define SMEM_U32 (4 * AS_SZ + 4 * WS_SZ)      // 17920
#define SMEM_BYTES (SMEM_U32 * 4)             // 71680

// ---------------- scratch (static device globals; no allocation) -----------
__device__ float g_h  [(size_t)BROWS * 200];
__device__ float g_g  [(size_t)BROWS * 800];
__device__ float g_hp [(size_t)BROWS * 200];
__device__ float g_p  [(size_t)BROWS * 200];
__device__ float g_eps[(size_t)BROWS * 100];
__device__ float g_sm [(size_t)BROWS * 100];
__device__ float g_wgru[400 * 800];

// packed bf16-pair weight planes: [Kpad/2][N] u32, Kpad = round_up(K,32)
#define WP_SA   0                       // 80*200   = 16000
#define WP_GRU  16000                   // 208*800  = 166400
#define WP_BP   182400                  // 112*200  = 22400
#define WP_SP   204800                  // 112*200  = 22400
#define WP_BQ   227200                  // 624*200  = 124800
#define WP_SQ   352000                  // 112*200  = 22400
#define WP_TOTAL 374400
__device__ uint32_t g_wp1[WP_TOTAL];
__device__ uint32_t g_wp2[WP_TOTAL];

// ---------------------------------------------------------------------------
// Threefry-2x32 (partitionable), key = (0, 42)
// ---------------------------------------------------------------------------
#define TFR(r) do { x0 += x1; x1 = (x1 << (r)) | (x1 >> (32 - (r))); x1 ^= x0; } while (0)

__device__ __forceinline__ void threefry2x32_0_42(uint32_t& x0, uint32_t& x1) {
    const uint32_t k0 = 0u;
    const uint32_t k1 = 42u;
    const uint32_t k2 = 0x1BD11BDAu ^ 0u ^ 42u;
    x0 += k0; x1 += k1;
    TFR(13); TFR(15); TFR(26); TFR(6);   x0 += k1; x1 += k2 + 1u;
    TFR(17); TFR(29); TFR(16); TFR(24);  x0 += k2; x1 += k0 + 2u;
    TFR(13); TFR(15); TFR(26); TFR(6);   x0 += k0; x1 += k1 + 3u;
    TFR(17); TFR(29); TFR(16); TFR(24);  x0 += k1; x1 += k2 + 4u;
    TFR(13); TFR(15); TFR(26); TFR(6);   x0 += k2; x1 += k0 + 5u;
}

__device__ __forceinline__ float bits_to_normal(uint32_t bits) {
    float f = __uint_as_float((bits >> 9) | 0x3f800000u) - 1.0f;
    const float lo = -0.99999994f;
    const float range = 2.0f;
    float u = __fadd_rn(__fmul_rn(f, range), lo);
    u = fmaxf(lo, u);
    return __fmul_rn(1.41421356f, erfinvf(u));
}

__global__ void eps_kernel(float* __restrict__ eps, int n) {
    int i = blockIdx.x * blockDim.x + threadIdx.x;
    if (i >= n) return;
    uint32_t x0 = 0u;
    uint32_t x1 = (uint32_t)i;
    threefry2x32_0_42(x0, x1);
    eps[i] = bits_to_normal(x0 ^ x1);
}

__global__ void premult_kernel(const float* __restrict__ st, const float* __restrict__ nt,
                               float* __restrict__ out, int n) {
    int i = blockIdx.x * blockDim.x + threadIdx.x;
    if (i >= n) return;
    out[i] = st[i] * nt[i / 100];
}

// ---------------------------------------------------------------------------
// GRU weight pack
// ---------------------------------------------------------------------------
__global__ void build_wgru_kernel(const float* __restrict__ W_ir, const float* __restrict__ W_iz,
                                  const float* __restrict__ W_in, const float* __restrict__ W_hr,
                                  const float* __restrict__ W_hz, const float* __restrict__ W_hn,
                                  float* __restrict__ wg) {
    int idx = blockIdx.x * blockDim.x + threadIdx.x;
    if (idx >= 400 * 800) return;
    int k = idx / 800, c = idx - k * 800;
    int blk = c / 200, j = c - blk * 200;
    float v = 0.0f;
    if (k < 200) {
        int o = k * 200 + j;
        if (blk == 0) v = W_ir[o];
        else if (blk == 1) v = W_iz[o];
        else if (blk == 2) v = W_in[o];
    } else {
        int o = (k - 200) * 200 + j;
        if (blk == 0) v = W_hr[o];
        else if (blk == 1) v = W_hz[o];
        else if (blk == 3) v = W_hn[o];
    }
    wg[idx] = v;
}

// ---------------------------------------------------------------------------
// Pack+split weights: W[K x N] f32 -> p1/p2 [Kpad/2][N] u32 (bf16 k-pairs)
// ---------------------------------------------------------------------------
__device__ __forceinline__ uint32_t pack2(__nv_bfloat16 lo, __nv_bfloat16 hi) {
    return (uint32_t)__bfloat16_as_ushort(lo) | ((uint32_t)__bfloat16_as_ushort(hi) << 16);
}

__global__ void psplit_kernel(const float* __restrict__ W, int K, int N, int ldw, int Kpad,
                              uint32_t* __restrict__ p1, uint32_t* __restrict__ p2) {
    int idx = blockIdx.x * blockDim.x + threadIdx.x;
    int total = (Kpad / 2) * N;
    if (idx >= total) return;
    int k2 = idx / N, n = idx - k2 * N;
    int k = 2 * k2;
    float v0 = (k     < K) ? W[(size_t)k       * ldw + n] : 0.0f;
    float v1 = (k + 1 < K) ? W[(size_t)(k + 1) * ldw + n] : 0.0f;
    __nv_bfloat16 a0 = __float2bfloat16_rn(v0);
    __nv_bfloat16 a1 = __float2bfloat16_rn(v1);
    __nv_bfloat16 b0 = __float2bfloat16_rn(v0 - __bfloat162float(a0));
    __nv_bfloat16 b1 = __float2bfloat16_rn(v1 - __bfloat162float(a1));
    p1[idx] = pack2(a0, a1);
    p2[idx] = pack2(b0, b1);
}

// ---------------------------------------------------------------------------
// mma + cp.async helpers
// ---------------------------------------------------------------------------
#define MMA_BF16(d, a, b0, b1)                                                \
    asm volatile(                                                             \
        "mma.sync.aligned.m16n8k16.row.col.f32.bf16.bf16.f32 "                \
        "{%0,%1,%2,%3}, {%4,%5,%6,%7}, {%8,%9}, {%0,%1,%2,%3};"               \
        : "+f"((d)[0]), "+f"((d)[1]), "+f"((d)[2]), "+f"((d)[3])              \
        : "r"((a)[0]), "r"((a)[1]), "r"((a)[2]), "r"((a)[3]), "r"(b0), "r"(b1))

#define CP_ASYNC16(dst_u32addr, src_ptr)                                      \
    asm volatile("cp.async.cg.shared.global [%0], [%1], 16;"                  \
                 :: "r"(dst_u32addr), "l"(src_ptr))
#define CP_COMMIT() asm volatile("cp.async.commit_group;" ::: "memory")
#define CP_WAIT0()  asm volatile("cp.async.wait_group 0;"  ::: "memory")

// ---------------------------------------------------------------------------
// bf16x2 tensor-core GEMM: C[64 x 200/blk] = act(concat(A0,A1) @ W + bias)
// ---------------------------------------------------------------------------
template<bool RELU, bool HASBIAS>
__global__ void __launch_bounds__(GTHREADS, 2)
gemm_kernel(const float* __restrict__ A0, const float* __restrict__ A1,
            int c0, int c1, int K, int Kpad,
            const uint32_t* __restrict__ P1, const uint32_t* __restrict__ P2,
            int ldwp,
            const float* __restrict__ bias, float* __restrict__ C, int ldc) {
    extern __shared__ uint32_t su[];
    uint32_t sb;
    asm("{ .reg .u64 t; cvta.to.shared.u64 t, %1; cvt.u32.u64 %0, t; }"
        : "=r"(sb) : "l"(su));

    const int tid  = threadIdx.x;
    const int lane = tid & 31;
    const int wq   = tid >> 5;
    const int mq   = wq >> 1;            // 0..3
    const int nq   = wq & 1;             // 0..1
    const int g    = lane >> 2;
    const int q    = lane & 3;
    const int row0 = blockIdx.x * BM;
    const int col0 = blockIdx.y * BN;
    const int j0   = nq * 13;
    const int mrow = mq * 16 + g;

    float acc[13][4];
    #pragma unroll
    for (int j = 0; j < 13; j++)
        #pragma unroll
        for (int t = 0; t < 4; t++) acc[j][t] = 0.0f;

    const int ntiles = Kpad / KC;

    // ---- W stage via cp.async: 1600 uint4 per tile (2 splits x 800) ----
    auto stage_w = [&](int tile, int buf) {
        for (int e = tid; e < 1600; e += GTHREADS) {
            int s   = (e >= 800);
            int r   = e - s * 800;
            int k2  = r / 50;
            int n4  = (r - k2 * 50) * 4;
            const uint32_t* src = (s ? P2 : P1)
                + (size_t)(tile * 16 + k2) * ldwp + col0 + n4;
            uint32_t dst = sb + (OFF_W(buf, s) + k2 * BN + n4) * 4;
            CP_ASYNC16(dst, src);
        }
    };

    // ---- prologue: tile 0 ----
    stage_w(0, 0);
    CP_COMMIT();
    #pragma unroll
    for (int i = 0; i < 4; i++) {
        int e = tid + i * GTHREADS;      // < 1024
        int m = e >> 4, k2 = e & 15;
        int k = 2 * k2;
        int row = row0 + m;
        float v0 = 0.0f, v1 = 0.0f;
        if (k < K) {
            const float* src = (k < c0) ? (A0 + (size_t)row * c0 + k)
                                        : (A1 + (size_t)row * c1 + (k - c0));
            float2 vv = *(const float2*)src;
            v0 = vv.x; v1 = vv.y;
        }
        __nv_bfloat16 x1 = __float2bfloat16_rn(v0);
        __nv_bfloat16 y1 = __float2bfloat16_rn(v1);
        __nv_bfloat16 x2 = __float2bfloat16_rn(v0 - __bfloat162float(x1));
        __nv_bfloat16 y2 = __float2bfloat16_rn(v1 - __bfloat162float(y1));
        su[OFF_A(0, 0) + m * AS_P + k2] = pack2(x1, y1);
        su[OFF_A(0, 1) + m * AS_P + k2] = pack2(x2, y2);
    }
    CP_WAIT0();
    __syncthreads();

    for (int t = 0; t < ntiles; t++) {
        const int buf = t & 1;
        const bool has_next = (t + 1 < ntiles);

        float2 apf[4];
        if (has_next) {
            stage_w(t + 1, buf ^ 1);
            CP_COMMIT();
            int k0n = (t + 1) * KC;
            #pragma unroll
            for (int i = 0; i < 4; i++) {
                int e = tid + i * GTHREADS;
                int m = e >> 4, k2 = e & 15;
                int k = k0n + 2 * k2;
                int row = row0 + m;
                float2 vv = make_float2(0.0f, 0.0f);
                if (k < K) {
                    const float* src = (k < c0) ? (A0 + (size_t)row * c0 + k)
                                                : (A1 + (size_t)row * c1 + (k - c0));
                    vv = *(const float2*)src;
                }
                apf[i] = vv;
            }
        }

        // ---- compute from smem[buf] ----
        const uint32_t* A1s = su + OFF_A(buf, 0);
        const uint32_t* A2s = su + OFF_A(buf, 1);
        const uint32_t* W1s = su + OFF_W(buf, 0);
        const uint32_t* W2s = su + OFF_W(buf, 1);
        #pragma unroll
        for (int ks = 0; ks < 2; ks++) {
            const int kb = ks * 8;
            uint32_t a1[4], a2[4];
            a1[0] = A1s[mrow * AS_P + kb + q];
            a1[1] = A1s[(mrow + 8) * AS_P + kb + q];
            a1[2] = A1s[mrow * AS_P + kb + q + 4];
            a1[3] = A1s[(mrow + 8) * AS_P + kb + q + 4];
            a2[0] = A2s[mrow * AS_P + kb + q];
            a2[1] = A2s[(mrow + 8) * AS_P + kb + q];
            a2[2] = A2s[mrow * AS_P + kb + q + 4];
            a2[3] = A2s[(mrow + 8) * AS_P + kb + q + 4];
            #pragma unroll
            for (int j = 0; j < 13; j++) {
                if (j0 + j < 25) {
                    int n = (j0 + j) * 8 + g;
                    uint32_t b10 = W1s[(kb + q) * BN + n];
                    uint32_t b11 = W1s[(kb + q + 4) * BN + n];
                    uint32_t b20 = W2s[(kb + q) * BN + n];
                    uint32_t b21 = W2s[(kb + q + 4) * BN + n];
                    MMA_BF16(acc[j], a1, b10, b11);   // a1*b1
                    MMA_BF16(acc[j], a2, b10, b11);   // a2*b1
                    MMA_BF16(acc[j], a1, b20, b21);   // a1*b2
                }
            }
        }

        if (has_next) {
            const int nb = buf ^ 1;
            #pragma unroll
            for (int i = 0; i < 4; i++) {
                int e = tid + i * GTHREADS;
                int m = e >> 4, k2 = e & 15;
                float v0 = apf[i].x, v1 = apf[i].y;
                __nv_bfloat16 x1 = __float2bfloat16_rn(v0);
                __nv_bfloat16 y1 = __float2bfloat16_rn(v1);
                __nv_bfloat16 x2 = __float2bfloat16_rn(v0 - __bfloat162float(x1));
                __nv_bfloat16 y2 = __float2bfloat16_rn(v1 - __bfloat162float(y1));
                su[OFF_A(nb, 0) + m * AS_P + k2] = pack2(x1, y1);
                su[OFF_A(nb, 1) + m * AS_P + k2] = pack2(x2, y2);
            }
        }
        CP_WAIT0();
        __syncthreads();
    }

    // ---- epilogue ----
    const int r0 = row0 + mrow;
    #pragma unroll
    for (int j = 0; j < 13; j++) {
        if (j0 + j < 25) {
            int col = col0 + (j0 + j) * 8 + 2 * q;
            float v0 = acc[j][0], v1 = acc[j][1], v2 = acc[j][2], v3 = acc[j][3];
            if (HASBIAS) {
                float bb0 = bias[col], bb1 = bias[col + 1];
                v0 += bb0; v1 += bb1; v2 += bb0; v3 += bb1;
            }
            if (RELU) {
                v0 = fmaxf(v0, 0.0f); v1 = fmaxf(v1, 0.0f);
                v2 = fmaxf(v2, 0.0f); v3 = fmaxf(v3, 0.0f);
            }
            *(float2*)&C[(size_t)r0 * ldc + col]       = make_float2(v0, v1);
            *(float2*)&C[(size_t)(r0 + 8) * ldc + col] = make_float2(v2, v3);
        }
    }
}

// ---------------------------------------------------------------------------
// GRU combine: belief = (1-z)*n + z*h
// ---------------------------------------------------------------------------
__global__ void gru_combine_kernel(const float* __restrict__ g, const float* __restrict__ h,
                                   const float* __restrict__ b_ir, const float* __restrict__ b_iz,
                                   const float* __restrict__ b_in, const float* __restrict__ b_hn,
                                   float* __restrict__ belief) {
    int i = blockIdx.x * blockDim.x + threadIdx.x;
    if (i >= BROWS * 200) return;
    int b = i / 200, j = i - b * 200;
    const float* gr = g + (size_t)b * 800;
    float r  = 1.0f / (1.0f + expf(-(gr[j]       + b_ir[j])));
    float z  = 1.0f / (1.0f + expf(-(gr[200 + j] + b_iz[j])));
    float nn = tanhf(gr[400 + j] + b_in[j] + r * (gr[600 + j] + b_hn[j]));
    float hv = h[i];
    belief[i] = (1.0f - z) * nn + z * hv;
}

// ---------------------------------------------------------------------------
// Distribution epilogue
// ---------------------------------------------------------------------------
__global__ void dist_kernel(const float* __restrict__ p, const float* __restrict__ eps,
                            float* __restrict__ st, float* __restrict__ mean,
                            float* __restrict__ stddev) {
    int i = blockIdx.x * blockDim.x + threadIdx.x;
    if (i >= BROWS * 100) return;
    int b = i / 100, d = i - b * 100;
    float m   = p[(size_t)b * 200 + d];
    float raw = p[(size_t)b * 200 + 100 + d];
    float sp  = (raw > 0.0f) ? (raw + log1pf(expf(-raw))) : log1pf(expf(raw));
    float s   = sp + 0.1f;
    mean[i]   = m;
    stddev[i] = s;
    st[i]     = m + s * eps[i];
}

// ---------------------------------------------------------------------------
extern "C" void kernel_launch(void* const* d_in, const int* in_sizes, int n_in,
                              void* d_out, int out_size) {
    const float* prev_state   = (const float*)d_in[0];
    const float* prev_action  = (const float*)d_in[1];
    const float* prev_belief  = (const float*)d_in[2];
    const float* observation  = (const float*)d_in[3];
    const float* nonterminals = (const float*)d_in[4];
    const float* W_sa = (const float*)d_in[5];  const float* b_sa = (const float*)d_in[6];
    const float* W_ir = (const float*)d_in[7];  const float* b_ir = (const float*)d_in[8];
    const float* W_iz = (const float*)d_in[9];  const float* b_iz = (const float*)d_in[10];
    const float* W_in = (const float*)d_in[11]; const float* b_in = (const float*)d_in[12];
    const float* W_hr = (const float*)d_in[13];
    const float* W_hz = (const float*)d_in[14];
    const float* W_hn = (const float*)d_in[15]; const float* b_hn = (const float*)d_in[16];
    const float* W_bp = (const float*)d_in[17]; const float* b_bp = (const float*)d_in[18];
    const float* W_sp = (const float*)d_in[19]; const float* b_sp = (const float*)d_in[20];
    const float* W_bq = (const float*)d_in[21]; const float* b_bq = (const float*)d_in[22];
    const float* W_sq = (const float*)d_in[23]; const float* b_sq = (const float*)d_in[24];

    float* out = (float*)d_out;

    float *h, *g, *hp, *p, *eps, *sm, *wgru;
    uint32_t *wp1, *wp2;
    cudaGetSymbolAddress((void**)&h,    g_h);
    cudaGetSymbolAddress((void**)&g,    g_g);
    cudaGetSymbolAddress((void**)&hp,   g_hp);
    cudaGetSymbolAddress((void**)&p,    g_p);
    cudaGetSymbolAddress((void**)&eps,  g_eps);
    cudaGetSymbolAddress((void**)&sm,   g_sm);
    cudaGetSymbolAddress((void**)&wgru, g_wgru);
    cudaGetSymbolAddress((void**)&wp1,  g_wp1);
    cudaGetSymbolAddress((void**)&wp2,  g_wp2);

    cudaFuncSetAttribute(gemm_kernel<true, true>,
                         cudaFuncAttributeMaxDynamicSharedMemorySize, SMEM_BYTES);
    cudaFuncSetAttribute(gemm_kernel<false, false>,
                         cudaFuncAttributeMaxDynamicSharedMemorySize, SMEM_BYTES);

    const size_t oBelief    = 0;
    const size_t oPriorSt   = (size_t)BROWS * 200;
    const size_t oPriorMean = (size_t)BROWS * 300;
    const size_t oPriorStd  = (size_t)BROWS * 400;
    const size_t oPostSt    = (size_t)BROWS * 500;
    const size_t oPostMean  = (size_t)BROWS * 600;
    const size_t oPostStd   = (size_t)BROWS * 700;

    const int MB = BROWS / BM;   // 512 row blocks

    // ---- prep ----
    {
        int n = BROWS * 100;
        eps_kernel<<<(n + 255) / 256, 256>>>(eps, n);
        premult_kernel<<<(n + 255) / 256, 256>>>(prev_state, nonterminals, sm, n);
    }
    build_wgru_kernel<<<(400 * 800 + 255) / 256, 256>>>(W_ir, W_iz, W_in, W_hr, W_hz, W_hn, wgru);

    psplit_kernel<<<(16000  + 255) / 256, 256>>>(W_sa, 132,  200, 200, 160,  wp1 + WP_SA,  wp2 + WP_SA);
    psplit_kernel<<<(166400 + 255) / 256, 256>>>(wgru, 400,  800, 800, 416,  wp1 + WP_GRU, wp2 + WP_GRU);
    psplit_kernel<<<(22400  + 255) / 256, 256>>>(W_bp, 200,  200, 200, 224,  wp1 + WP_BP,  wp2 + WP_BP);
    psplit_kernel<<<(22400  + 255) / 256, 256>>>(W_sp, 200,  200, 200, 224,  wp1 + WP_SP,  wp2 + WP_SP);
    psplit_kernel<<<(124800 + 255) / 256, 256>>>(W_bq, 1224, 200, 200, 1248, wp1 + WP_BQ,  wp2 + WP_BQ);
    psplit_kernel<<<(22400  + 255) / 256, 256>>>(W_sq, 200,  200, 200, 224,  wp1 + WP_SQ,  wp2 + WP_SQ);

    // 3) h = relu([sm, action] @ W_sa + b_sa)   (K=132)
    gemm_kernel<true, true><<<dim3(MB, 1), GTHREADS, SMEM_BYTES>>>(
        sm, prev_action, 100, 32, 132, 160, wp1 + WP_SA, wp2 + WP_SA, 200, b_sa, h, 200);

    // 4) g = [prev_belief, h] @ Wgru            (K=400, N=800)
    gemm_kernel<false, false><<<dim3(MB, 4), GTHREADS, SMEM_BYTES>>>(
        prev_belief, h, 200, 200, 400, 416, wp1 + WP_GRU, wp2 + WP_GRU, 800, nullptr, g, 800);

    // 5) new_belief
    gru_combine_kernel<<<(BROWS * 200 + 255) / 256, 256>>>(
        g, h, b_ir, b_iz, b_in, b_hn, out + oBelief);

    // 6) hp = relu(belief @ W_bp + b_bp)        (K=200)
    gemm_kernel<true, true><<<dim3(MB, 1), GTHREADS, SMEM_BYTES>>>(
        out + oBelief, out + oBelief, 200, 200, 200, 224, wp1 + WP_BP, wp2 + WP_BP, 200, b_bp, hp, 200);

    // 7) p = relu(hp @ W_sp + b_sp)             (K=200)
    gemm_kernel<true, true><<<dim3(MB, 1), GTHREADS, SMEM_BYTES>>>(
        hp, hp, 200, 200, 200, 224, wp1 + WP_SP, wp2 + WP_SP, 200, b_sp, p, 200);

    // 8) prior outputs
    dist_kernel<<<(BROWS * 100 + 255) / 256, 256>>>(
        p, eps, out + oPriorSt, out + oPriorMean, out + oPriorStd);

    // 9) hq = relu([belief, obs] @ W_bq + b_bq) (K=1224)
    gemm_kernel<true, true><<<dim3(MB, 1), GTHREADS, SMEM_BYTES>>>(
        out + oBelief, observation, 200, 1024, 1224, 1248, wp1 + WP_BQ, wp2 + WP_BQ, 200, b_bq, hp, 200);

    // 10) p = relu(hq @ W_sq + b_sq)            (K=200)
    gemm_kernel<true, true><<<dim3(MB, 1), GTHREADS, SMEM_BYTES>>>(
        hp, hp, 200, 200, 200, 224, wp1 + WP_SQ, wp2 + WP_SQ, 200, b_sq, p, 200);

    // 11) posterior outputs
    dist_kernel<<<(BROWS * 100 + 255) / 256, 256>>>(
        p, eps, out + oPostSt, out + oPostMean, out + oPostStd);

    (void)in_sizes; (void)n_in; (void)out_size;
}